// round 6
// baseline (speedup 1.0000x reference)
#include <cuda_runtime.h>
#include <cuda_fp16.h>
#include <cstdint>

// Problem geometry: velocity (B=2, D=128, H=128, W=128, C=3) float32
#define B_  2
#define DIM 128
#define VOX_PER_B (DIM * DIM * DIM)          // 2097152 = 1<<21
#define N_VOX (B_ * VOX_PER_B)               // 4194304

// Shifted-pair layout: C[i] = (pack(v[i]), pack(v[i_next])) where i_next = i with
// x -> (x+1) mod 128. 16 B/voxel. One LDG.128 fetches both x-corners of a row.
__device__ uint4 g_bufA[N_VOX];
__device__ uint4 g_bufB[N_VOX];

static __device__ __forceinline__ uint2 pack_v(float vz, float vy, float vx)
{
    __half2 h0 = __floats2half2_rn(vz, vy);
    __half2 h1 = __floats2half2_rn(vx, 0.f);
    uint2 r;
    r.x = *(const unsigned int*)&h0;
    r.y = *(const unsigned int*)&h1;
    return r;
}

// -------- convert: fp32 float3 AoS -> shifted-pair fp16, fused 1/2^STEPS scale --------
// One warp handles one full x-row (128 voxels, 4 voxels/lane) so the x+1 neighbor
// (including the x=127 -> x=0 wrap) is always available via intra-warp shuffle.
__global__ __launch_bounds__(256)
void convert_kernel(const float* __restrict__ in, uint4* __restrict__ out, float s)
{
    int lane = threadIdx.x & 31;
    int row  = (blockIdx.x * 256 + threadIdx.x) >> 5;   // global row id, 0..32767
    int base = row * 128 + lane * 4;                     // first voxel of this lane

    const float4* in4 = (const float4*)in;
    int fb = row * 96 + lane * 3;                        // 12 floats = 3 float4
    float4 a = in4[fb + 0];
    float4 b = in4[fb + 1];
    float4 c = in4[fb + 2];

    uint2 p0 = pack_v(a.x * s, a.y * s, a.z * s);
    uint2 p1 = pack_v(a.w * s, b.x * s, b.y * s);
    uint2 p2 = pack_v(b.z * s, b.w * s, c.x * s);
    uint2 p3 = pack_v(c.y * s, c.z * s, c.w * s);

    unsigned nx = __shfl_sync(0xffffffffu, p0.x, (lane + 1) & 31);
    unsigned ny = __shfl_sync(0xffffffffu, p0.y, (lane + 1) & 31);

    out[base + 0] = make_uint4(p0.x, p0.y, p1.x, p1.y);
    out[base + 1] = make_uint4(p1.x, p1.y, p2.x, p2.y);
    out[base + 2] = make_uint4(p2.x, p2.y, p3.x, p3.y);
    out[base + 3] = make_uint4(p3.x, p3.y, nx, ny);
}

// -------- one squaring step on shifted-pair layout --------
// LAST=0: dst (shifted-pair fp16 scratch). LAST=1: dst3 (stride-3 fp32 out) + identity.
template <int LAST>
__global__ __launch_bounds__(256)
void gridexp_step(const uint4* __restrict__ src, uint4* __restrict__ dst,
                  float* __restrict__ dst3)
{
    const int idx = blockIdx.x * 256 + threadIdx.x;      // grid sized exactly

    const int b = idx >> 21;
    const int r = idx & (VOX_PER_B - 1);
    const int z = r >> 14;
    const int y = (r >> 7) & 127;
    const int x = r & 127;

    // own value = low half of C[idx]
    uint2 pv = __ldg((const uint2*)src + 2 * (size_t)idx);
    __half2 pv0 = *(const __half2*)&pv.x;
    __half2 pv1 = *(const __half2*)&pv.y;
    float2 f0 = __half22float2(pv0);
    float vz = f0.x, vy = f0.y;
    float vx = __low2float(pv1);

    float phz = (float)z + vz;
    float phy = (float)y + vy;
    float phx = (float)x + vx;

    int iz = __float2int_rd(phz);
    int iy = __float2int_rd(phy);
    int ix = __float2int_rd(phx);
    float wz1 = phz - (float)iz;
    float wy1 = phy - (float)iy;
    float wx1 = phx - (float)ix;
    float wz0 = 1.0f - wz1, wy0 = 1.0f - wy1, wx0 = 1.0f - wx1;

    int z0 = iz & 127, z1 = (iz + 1) & 127;
    int y0 = iy & 127, y1 = (iy + 1) & 127;
    int x0 = ix & 127;

    const int base = b << 21;
    int rows[4];
    rows[0] = base + (z0 << 14) + (y0 << 7) + x0;
    rows[1] = base + (z0 << 14) + (y1 << 7) + x0;
    rows[2] = base + (z1 << 14) + (y0 << 7) + x0;
    rows[3] = base + (z1 << 14) + (y1 << 7) + x0;

    __half2 wzy2[4];
    wzy2[0] = __float2half2_rn(wz0 * wy0);
    wzy2[1] = __float2half2_rn(wz0 * wy1);
    wzy2[2] = __float2half2_rn(wz1 * wy0);
    wzy2[3] = __float2half2_rn(wz1 * wy1);
    const __half2 wxlo = __float2half2_rn(wx0);
    const __half2 wxhi = __float2half2_rn(wx1);

    __half2 acc0 = __float2half2_rn(0.f);   // (sz, sy)
    __half2 acc1 = __float2half2_rn(0.f);   // (sx, ·)

#pragma unroll
    for (int rr = 0; rr < 4; ++rr) {
        uint4 q = __ldg(src + rows[rr]);     // (v[x0], v[x0+1]) wrap baked in
        __half2 wlo = __hmul2(wzy2[rr], wxlo);
        __half2 whi = __hmul2(wzy2[rr], wxhi);
        acc0 = __hfma2(wlo, *(const __half2*)&q.x, acc0);
        acc1 = __hfma2(wlo, *(const __half2*)&q.y, acc1);
        acc0 = __hfma2(whi, *(const __half2*)&q.z, acc0);
        acc1 = __hfma2(whi, *(const __half2*)&q.w, acc1);
    }

    float2 s0 = __half22float2(acc0);
    float oz = vz + s0.x;
    float oy = vy + s0.y;
    float ox = vx + __low2float(acc1);

    if (LAST) {
        float* o = dst3 + (size_t)idx * 3;
        o[0] = oz + (float)z;
        o[1] = oy + (float)y;
        o[2] = ox + (float)x;
    } else {
        // write C[idx] = (p_self, p_neighbor(x+1))
        __shared__ uint2 sb[8];              // lane-0 value of each warp
        const int w = threadIdx.x >> 5;
        const int lane = threadIdx.x & 31;

        uint2 p = pack_v(oz, oy, ox);
        if (lane == 0) sb[w] = p;
        __syncthreads();

        unsigned nx = __shfl_sync(0xffffffffu, p.x, (lane + 1) & 31);
        unsigned ny = __shfl_sync(0xffffffffu, p.y, (lane + 1) & 31);
        if (lane == 31) {
            // block = 2 rows of 128 (4 warps each); neighbor warp wraps within the row
            int nbw = (w & 4) | ((w + 1) & 3);
            uint2 q2 = sb[nbw];
            nx = q2.x;
            ny = q2.y;
        }
        dst[idx] = make_uint4(p.x, p.y, nx, ny);
    }
}

extern "C" void kernel_launch(void* const* d_in, const int* in_sizes, int n_in,
                              void* d_out, int out_size)
{
    (void)in_sizes; (void)n_in; (void)out_size;
    const float* vel = (const float*)d_in[0];
    float* out = (float*)d_out;

    uint4* bufA = nullptr;
    uint4* bufB = nullptr;
    cudaGetSymbolAddress((void**)&bufA, g_bufA);
    cudaGetSymbolAddress((void**)&bufB, g_bufB);

    const float scale = 1.0f / 256.0f;   // 1 / 2^STEPS, STEPS = 8

    // convert: one warp per x-row; 32768 rows total, 8 rows per 256-thread block
    convert_kernel<<<4096, 256>>>(vel, bufA, scale);

    const int blocks = N_VOX / 256;      // exact
    uint4* cur = bufA;
    uint4* nxt = bufB;
    for (int i = 0; i < 7; ++i) {
        gridexp_step<0><<<blocks, 256>>>(cur, nxt, nullptr);
        uint4* t = cur; cur = nxt; nxt = t;
    }
    gridexp_step<1><<<blocks, 256>>>(cur, nullptr, out);
}

// round 7
// speedup vs baseline: 1.1273x; 1.1273x over previous
#include <cuda_runtime.h>
#include <cuda_fp16.h>
#include <cstdint>

// Problem geometry: velocity (B=2, D=128, H=128, W=128, C=3) float32
#define B_  2
#define DIM 128
#define VOX_PER_B (DIM * DIM * DIM)          // 2097152 = 1<<21
#define N_VOX (B_ * VOX_PER_B)               // 4194304

// Ping-pong scratch: 8 B/voxel = (half2(vz,vy), half2(vx,0)) packed in uint2
__device__ uint2 g_bufA[N_VOX];
__device__ uint2 g_bufB[N_VOX];

static __device__ __forceinline__ uint2 pack_v(float vz, float vy, float vx)
{
    __half2 h0 = __floats2half2_rn(vz, vy);
    __half2 h1 = __floats2half2_rn(vx, 0.f);
    uint2 r;
    r.x = *(const unsigned int*)&h0;
    r.y = *(const unsigned int*)&h1;
    return r;
}

// -------- convert: float3 AoS fp32 input -> packed fp16, fused 1/2^STEPS scale --------
__global__ __launch_bounds__(256)
void convert_kernel(const float* __restrict__ in, uint2* __restrict__ out, float s)
{
    int t = blockIdx.x * blockDim.x + threadIdx.x;   // one thread = 4 voxels
    if (t >= N_VOX / 4) return;
    const float4* in4 = (const float4*)in;
    float4 a = in4[t * 3 + 0];
    float4 b = in4[t * 3 + 1];
    float4 c = in4[t * 3 + 2];
    out[t * 4 + 0] = pack_v(a.x * s, a.y * s, a.z * s);
    out[t * 4 + 1] = pack_v(a.w * s, b.x * s, b.y * s);
    out[t * 4 + 2] = pack_v(b.z * s, b.w * s, c.x * s);
    out[t * 4 + 3] = pack_v(c.y * s, c.z * s, c.w * s);
}

// interpolate one voxel: fp32 own value + weights, half2 gather accumulate
static __device__ __forceinline__ void interp_one(
    const uint2* __restrict__ src, int base, int z, int y, int x,
    uint2 pv, float& oz, float& oy, float& ox)
{
    __half2 pv0 = *(const __half2*)&pv.x;
    __half2 pv1 = *(const __half2*)&pv.y;
    float2 f0 = __half22float2(pv0);
    float vz = f0.x, vy = f0.y;
    float vx = __low2float(pv1);

    float phz = (float)z + vz;
    float phy = (float)y + vy;
    float phx = (float)x + vx;

    int iz = __float2int_rd(phz);
    int iy = __float2int_rd(phy);
    int ix = __float2int_rd(phx);
    float wz1 = phz - (float)iz;
    float wy1 = phy - (float)iy;
    float wx1 = phx - (float)ix;
    float wz0 = 1.0f - wz1, wy0 = 1.0f - wy1, wx0 = 1.0f - wx1;

    int z0 = iz & 127, z1 = (iz + 1) & 127;
    int y0 = iy & 127, y1 = (iy + 1) & 127;
    int x0 = ix & 127, x1 = (ix + 1) & 127;

    int rows[4];
    rows[0] = base + (z0 << 14) + (y0 << 7);
    rows[1] = base + (z0 << 14) + (y1 << 7);
    rows[2] = base + (z1 << 14) + (y0 << 7);
    rows[3] = base + (z1 << 14) + (y1 << 7);

    __half2 wzy2[4];
    wzy2[0] = __float2half2_rn(wz0 * wy0);
    wzy2[1] = __float2half2_rn(wz0 * wy1);
    wzy2[2] = __float2half2_rn(wz1 * wy0);
    wzy2[3] = __float2half2_rn(wz1 * wy1);
    const __half2 wxlo = __float2half2_rn(wx0);
    const __half2 wxhi = __float2half2_rn(wx1);

    // issue all 8 loads up front for max MLP
    uint2 q[8];
#pragma unroll
    for (int rr = 0; rr < 4; ++rr) {
        q[2 * rr + 0] = __ldg(src + rows[rr] + x0);
        q[2 * rr + 1] = __ldg(src + rows[rr] + x1);
    }

    __half2 acc0 = __float2half2_rn(0.f);   // (sz, sy)
    __half2 acc1 = __float2half2_rn(0.f);   // (sx, ·)
#pragma unroll
    for (int rr = 0; rr < 4; ++rr) {
        __half2 wlo = __hmul2(wzy2[rr], wxlo);
        __half2 whi = __hmul2(wzy2[rr], wxhi);
        acc0 = __hfma2(wlo, *(const __half2*)&q[2 * rr].x, acc0);
        acc1 = __hfma2(wlo, *(const __half2*)&q[2 * rr].y, acc1);
        acc0 = __hfma2(whi, *(const __half2*)&q[2 * rr + 1].x, acc0);
        acc1 = __hfma2(whi, *(const __half2*)&q[2 * rr + 1].y, acc1);
    }

    float2 s0 = __half22float2(acc0);
    oz = vz + s0.x;
    oy = vy + s0.y;
    ox = vx + __low2float(acc1);
}

// -------- one squaring step: 2 adjacent-x voxels per thread --------
// LAST=0: dst (packed fp16 scratch). LAST=1: dst3 (stride-3 fp32 output) + identity grid.
template <int LAST>
__global__ __launch_bounds__(256, 6)
void gridexp_step(const uint2* __restrict__ src, uint2* __restrict__ dst,
                  float* __restrict__ dst3)
{
    const int t = blockIdx.x * 256 + threadIdx.x;
    const int idx = t * 2;                    // even voxel index

    const int b = idx >> 21;
    const int r = idx & (VOX_PER_B - 1);
    const int z = r >> 14;
    const int y = (r >> 7) & 127;
    const int x = r & 127;                    // even
    const int base = b << 21;

    // own values: one LDG.128 for both voxels
    uint4 own = __ldg((const uint4*)src + t);
    uint2 pv0 = make_uint2(own.x, own.y);
    uint2 pv1 = make_uint2(own.z, own.w);

    float oz0, oy0, ox0, oz1, oy1, ox1;
    interp_one(src, base, z, y, x,     pv0, oz0, oy0, ox0);
    interp_one(src, base, z, y, x + 1, pv1, oz1, oy1, ox1);

    if (LAST) {
        float* o = dst3 + (size_t)idx * 3;    // 24B-aligned (idx even) -> 8B ok
        ((float2*)o)[0] = make_float2(oz0 + (float)z, oy0 + (float)y);
        ((float2*)o)[1] = make_float2(ox0 + (float)x, oz1 + (float)z);
        ((float2*)o)[2] = make_float2(oy1 + (float)y, ox1 + (float)(x + 1));
    } else {
        uint2 p0 = pack_v(oz0, oy0, ox0);
        uint2 p1 = pack_v(oz1, oy1, ox1);
        ((uint4*)dst)[t] = make_uint4(p0.x, p0.y, p1.x, p1.y);
    }
}

extern "C" void kernel_launch(void* const* d_in, const int* in_sizes, int n_in,
                              void* d_out, int out_size)
{
    (void)in_sizes; (void)n_in; (void)out_size;
    const float* vel = (const float*)d_in[0];
    float* out = (float*)d_out;

    uint2* bufA = nullptr;
    uint2* bufB = nullptr;
    cudaGetSymbolAddress((void**)&bufA, g_bufA);
    cudaGetSymbolAddress((void**)&bufB, g_bufB);

    const float scale = 1.0f / 256.0f;   // 1 / 2^STEPS, STEPS = 8
    const int threads = 256;

    convert_kernel<<<(N_VOX / 4 + threads - 1) / threads, threads>>>(vel, bufA, scale);

    const int blocks = N_VOX / 2 / threads;   // exact: 8192
    uint2* cur = bufA;
    uint2* nxt = bufB;
    for (int i = 0; i < 7; ++i) {
        gridexp_step<0><<<blocks, threads>>>(cur, nxt, nullptr);
        uint2* t = cur; cur = nxt; nxt = t;
    }
    gridexp_step<1><<<blocks, threads>>>(cur, nullptr, out);
}

// round 8
// speedup vs baseline: 1.1403x; 1.0116x over previous
#include <cuda_runtime.h>
#include <cuda_fp16.h>
#include <cstdint>

// Problem geometry: velocity (B=2, D=128, H=128, W=128, C=3) float32
#define B_  2
#define DIM 128
#define VOX_PER_B (DIM * DIM * DIM)          // 2097152 = 1<<21
#define N_VOX (B_ * VOX_PER_B)               // 4194304

// Ping-pong scratch: 8 B/voxel = (half2(vz,vy), half2(vx,0)) packed in uint2
__device__ uint2 g_bufA[N_VOX];
__device__ uint2 g_bufB[N_VOX];

static __device__ __forceinline__ uint2 pack_v(float vz, float vy, float vx)
{
    __half2 h0 = __floats2half2_rn(vz, vy);
    __half2 h1 = __floats2half2_rn(vx, 0.f);
    uint2 r;
    r.x = *(const unsigned int*)&h0;
    r.y = *(const unsigned int*)&h1;
    return r;
}

// -------- convert: float3 AoS fp32 input -> packed fp16, fused 1/2^STEPS scale --------
__global__ __launch_bounds__(256)
void convert_kernel(const float* __restrict__ in, uint2* __restrict__ out, float s)
{
    int t = blockIdx.x * blockDim.x + threadIdx.x;   // one thread = 4 voxels
    if (t >= N_VOX / 4) return;
    const float4* in4 = (const float4*)in;
    float4 a = in4[t * 3 + 0];
    float4 b = in4[t * 3 + 1];
    float4 c = in4[t * 3 + 2];
    out[t * 4 + 0] = pack_v(a.x * s, a.y * s, a.z * s);
    out[t * 4 + 1] = pack_v(a.w * s, b.x * s, b.y * s);
    out[t * 4 + 2] = pack_v(b.z * s, b.w * s, c.x * s);
    out[t * 4 + 3] = pack_v(c.y * s, c.z * s, c.w * s);
}

// -------- one squaring step: fp16 storage, half2 gather math --------
// Own-row corner pair is served from warp registers via shuffle; the global
// load for that row is predicated off. Out-of-window / wrapped cases fall
// back to the global load (always correct).
// LAST=0: dst (packed fp16 scratch). LAST=1: dst3 (stride-3 fp32 output) + identity grid.
template <int LAST>
__global__ __launch_bounds__(256)
void gridexp_step(const uint2* __restrict__ src, uint2* __restrict__ dst,
                  float* __restrict__ dst3)
{
    const int idx = blockIdx.x * 256 + threadIdx.x;   // grid sized exactly

    const int b = idx >> 21;
    const int r = idx & (VOX_PER_B - 1);
    const int z = r >> 14;
    const int y = (r >> 7) & 127;
    const int x = r & 127;
    const int lane = threadIdx.x & 31;
    const int base = b << 21;

    // own value
    uint2 pv = src[idx];
    __half2 pv0 = *(const __half2*)&pv.x;
    __half2 pv1 = *(const __half2*)&pv.y;
    float2 f0 = __half22float2(pv0);
    float vz = f0.x, vy = f0.y;
    float vx = __low2float(pv1);

    float phz = (float)z + vz;
    float phy = (float)y + vy;
    float phx = (float)x + vx;

    int iz = __float2int_rd(phz);
    int iy = __float2int_rd(phy);
    int ix = __float2int_rd(phx);
    float wz1 = phz - (float)iz;
    float wy1 = phy - (float)iy;
    float wx1 = phx - (float)ix;
    float wz0 = 1.0f - wz1, wy0 = 1.0f - wy1, wx0 = 1.0f - wx1;

    int z0 = iz & 127, z1 = (iz + 1) & 127;
    int y0 = iy & 127, y1 = (iy + 1) & 127;
    int x0 = ix & 127, x1 = (ix + 1) & 127;

    int rows[4];
    rows[0] = base + (z0 << 14) + (y0 << 7);
    rows[1] = base + (z0 << 14) + (y1 << 7);
    rows[2] = base + (z1 << 14) + (y0 << 7);
    rows[3] = base + (z1 << 14) + (y1 << 7);
    const int ownrow = base + (z << 14) + (y << 7);

    // own-row corner pair via warp shuffle (warp holds x in [x-lane, x-lane+31])
    const int j0 = ix - (x - lane);                 // unwrapped corner0 lane index
    const bool xin = (unsigned)j0 <= 30u;           // corners j0, j0+1 both in window
    unsigned s0x = __shfl_sync(0xffffffffu, pv.x, j0 & 31);
    unsigned s0y = __shfl_sync(0xffffffffu, pv.y, j0 & 31);
    unsigned s1x = __shfl_sync(0xffffffffu, pv.x, (j0 + 1) & 31);
    unsigned s1y = __shfl_sync(0xffffffffu, pv.y, (j0 + 1) & 31);

    __half2 wzy2[4];
    wzy2[0] = __float2half2_rn(wz0 * wy0);
    wzy2[1] = __float2half2_rn(wz0 * wy1);
    wzy2[2] = __float2half2_rn(wz1 * wy0);
    wzy2[3] = __float2half2_rn(wz1 * wy1);
    const __half2 wxlo = __float2half2_rn(wx0);
    const __half2 wxhi = __float2half2_rn(wx1);

    __half2 acc0 = __float2half2_rn(0.f);   // (sz, sy)
    __half2 acc1 = __float2half2_rn(0.f);   // (sx, ·)

#pragma unroll
    for (int rr = 0; rr < 4; ++rr) {
        const bool useshfl = xin && (rows[rr] == ownrow);
        uint2 q0, q1;
        q0.x = s0x; q0.y = s0y;
        q1.x = s1x; q1.y = s1y;
        if (!useshfl) {
            q0 = __ldg(src + rows[rr] + x0);
            q1 = __ldg(src + rows[rr] + x1);
        }
        __half2 wlo = __hmul2(wzy2[rr], wxlo);
        __half2 whi = __hmul2(wzy2[rr], wxhi);
        acc0 = __hfma2(wlo, *(const __half2*)&q0.x, acc0);
        acc1 = __hfma2(wlo, *(const __half2*)&q0.y, acc1);
        acc0 = __hfma2(whi, *(const __half2*)&q1.x, acc0);
        acc1 = __hfma2(whi, *(const __half2*)&q1.y, acc1);
    }

    float2 s0 = __half22float2(acc0);
    float oz = vz + s0.x;
    float oy = vy + s0.y;
    float ox = vx + __low2float(acc1);

    if (LAST) {
        float* o = dst3 + (size_t)idx * 3;
        o[0] = oz + (float)z;
        o[1] = oy + (float)y;
        o[2] = ox + (float)x;
    } else {
        dst[idx] = pack_v(oz, oy, ox);
    }
}

extern "C" void kernel_launch(void* const* d_in, const int* in_sizes, int n_in,
                              void* d_out, int out_size)
{
    (void)in_sizes; (void)n_in; (void)out_size;
    const float* vel = (const float*)d_in[0];
    float* out = (float*)d_out;

    uint2* bufA = nullptr;
    uint2* bufB = nullptr;
    cudaGetSymbolAddress((void**)&bufA, g_bufA);
    cudaGetSymbolAddress((void**)&bufB, g_bufB);

    const float scale = 1.0f / 256.0f;   // 1 / 2^STEPS, STEPS = 8
    const int threads = 256;

    convert_kernel<<<(N_VOX / 4 + threads - 1) / threads, threads>>>(vel, bufA, scale);

    const int blocks = N_VOX / threads;  // exact: 16384
    uint2* cur = bufA;
    uint2* nxt = bufB;
    for (int i = 0; i < 7; ++i) {
        gridexp_step<0><<<blocks, threads>>>(cur, nxt, nullptr);
        uint2* t = cur; cur = nxt; nxt = t;
    }
    gridexp_step<1><<<blocks, threads>>>(cur, nullptr, out);
}